// round 1
// baseline (speedup 1.0000x reference)
#include <cuda_runtime.h>
#include <math.h>

#define BB   8
#define TT   4096
#define CC   512
#define HH   512
#define NOUT 1536
#define NC   16
#define LCH  256    // TT / NC

#define BM 128
#define BN 128
#define BK 16
#define XPAD 20     // stride 20 floats -> conflict-free frag loads (20*r mod 32 hits {0,4,...,28})

// -------- scratch (device globals; no allocation allowed) --------
__device__ float g_zfo [BB * TT * NOUT];   // post-activation z|f|o, [B,T,1536]
__device__ float g_out1[BB * TT * HH];     // layer-1 output
__device__ float g_cA  [BB * NC * HH];     // per-chunk prod(f)
__device__ float g_cB  [BB * NC * HH];     // per-chunk local h_end
__device__ float g_hs  [BB * NC * HH];     // per-chunk h_start

__device__ __forceinline__ unsigned f2tf(float x) {
    unsigned u;
    asm("cvt.rna.tf32.f32 %0, %1;" : "=r"(u) : "f"(x));
    return u;
}

__device__ __forceinline__ void mma8(float* c, const unsigned* a, unsigned b0, unsigned b1) {
    asm volatile(
        "mma.sync.aligned.m16n8k8.row.col.f32.tf32.tf32.f32 "
        "{%0,%1,%2,%3}, {%4,%5,%6,%7}, {%8,%9}, {%0,%1,%2,%3};\n"
        : "+f"(c[0]), "+f"(c[1]), "+f"(c[2]), "+f"(c[3])
        : "r"(a[0]), "r"(a[1]), "r"(a[2]), "r"(a[3]), "r"(b0), "r"(b1));
}

__device__ __forceinline__ float act(float v, int ng) {
    if (ng < HH) return tanhf(v);
    return 1.0f / (1.0f + expf(-v));
}

// GEMM: ZFO[b,t,n] = act( sum_c W[n,c,0]*X[b,t-1,c] + W[n,c,1]*X[b,t,c] + bias[n] )
// grid (256, 12), block 256.  layer selects X source (input x vs g_out1).
__global__ void __launch_bounds__(256) qrnn_gemm(
    int layer, const float* __restrict__ Xin,
    const float* __restrict__ W, const float* __restrict__ bias)
{
    __shared__ unsigned sX[129 * XPAD];
    __shared__ unsigned sW[2 * BN * XPAD];

    const float* X = layer ? g_out1 : Xin;

    const int tid  = threadIdx.x;
    const int mt   = blockIdx.x;
    const int nt   = blockIdx.y;
    const int b    = mt >> 5;
    const int t0   = (mt & 31) * BM;
    const int warp = tid >> 5, lane = tid & 31;
    const int wm   = warp >> 2, wn = warp & 3;   // 2 x 4 warp grid
    const int gr   = lane >> 2, tg = lane & 3;

    float acc[4][4][4];
#pragma unroll
    for (int i = 0; i < 4; i++)
#pragma unroll
        for (int j = 0; j < 4; j++)
#pragma unroll
            for (int q = 0; q < 4; q++) acc[i][j][q] = 0.0f;

    const float* Xb = X + (size_t)b * TT * CC;

    for (int kc = 0; kc < CC; kc += BK) {
        // ---- load X tile: rows t0-1 .. t0+127 (129 rows) x 16 cols, as float4 ----
        for (int idx = tid; idx < 129 * 4; idx += 256) {
            int r = idx >> 2, c4 = idx & 3;
            int t = t0 - 1 + r;
            float4 v = make_float4(0.f, 0.f, 0.f, 0.f);
            if (t >= 0) v = *(const float4*)(Xb + (size_t)t * CC + kc + c4 * 4);
            unsigned* p = &sX[r * XPAD + c4 * 4];
            p[0] = f2tf(v.x); p[1] = f2tf(v.y); p[2] = f2tf(v.z); p[3] = f2tf(v.w);
        }
        // ---- load W tile: 128 n x 16 c, both taps (float2 per (n,c)) ----
        for (int idx = tid; idx < BN * BK; idx += 256) {
            int n = idx >> 4, c = idx & 15;
            float2 wv = *(const float2*)(W + ((size_t)(nt * BN + n) * CC + (kc + c)) * 2);
            sW[0 * BN * XPAD + n * XPAD + c] = f2tf(wv.x);
            sW[1 * BN * XPAD + n * XPAD + c] = f2tf(wv.y);
        }
        __syncthreads();

#pragma unroll
        for (int k8 = 0; k8 < 2; ++k8) {
            int cb = k8 * 8;
#pragma unroll
            for (int tap = 0; tap < 2; ++tap) {
                unsigned a[4][4];
#pragma unroll
                for (int i = 0; i < 4; i++) {
                    int r0 = wm * 64 + i * 16 + gr + tap;
                    a[i][0] = sX[r0 * XPAD + cb + tg];
                    a[i][1] = sX[(r0 + 8) * XPAD + cb + tg];
                    a[i][2] = sX[r0 * XPAD + cb + tg + 4];
                    a[i][3] = sX[(r0 + 8) * XPAD + cb + tg + 4];
                }
#pragma unroll
                for (int j = 0; j < 4; j++) {
                    int n0 = wn * 32 + j * 8 + gr;
                    unsigned b0 = sW[tap * BN * XPAD + n0 * XPAD + cb + tg];
                    unsigned b1 = sW[tap * BN * XPAD + n0 * XPAD + cb + tg + 4];
#pragma unroll
                    for (int i = 0; i < 4; i++) mma8(acc[i][j], a[i][0] == a[i][0] ? a[i] : a[i], b0, b1);
                }
            }
        }
        __syncthreads();
    }

    // ---- epilogue: bias + activation, store to g_zfo ----
#pragma unroll
    for (int j = 0; j < 4; j++) {
        int ng = nt * BN + wn * 32 + j * 8 + tg * 2;
        float bb0 = bias[ng], bb1 = bias[ng + 1];
#pragma unroll
        for (int i = 0; i < 4; i++) {
            int m0 = wm * 64 + i * 16 + gr;
            int tA = t0 + m0, tB = t0 + m0 + 8;
            size_t rowA = ((size_t)(b * TT + tA)) * NOUT;
            size_t rowB = ((size_t)(b * TT + tB)) * NOUT;
            g_zfo[rowA + ng]     = act(acc[i][j][0] + bb0, ng);
            g_zfo[rowA + ng + 1] = act(acc[i][j][1] + bb1, ng + 1);
            g_zfo[rowB + ng]     = act(acc[i][j][2] + bb0, ng);
            g_zfo[rowB + ng + 1] = act(acc[i][j][3] + bb1, ng + 1);
        }
    }
}

// pass 1: per (b, chunk, h) compute A = prod(f), Bv = chunk-local scan end.
// grid 512 (= B * NC * 4), block 128.
__global__ void __launch_bounds__(128) scan_pass1()
{
    int h  = (blockIdx.x & 3) * 128 + threadIdx.x;
    int ch = (blockIdx.x >> 2) & 15;
    int b  = blockIdx.x >> 6;
    const float* p = g_zfo + ((size_t)(b * TT + ch * LCH)) * NOUT + h;
    float A = 1.0f, hv = 0.0f;
#pragma unroll 4
    for (int i = 0; i < LCH; i++) {
        float z = p[0];
        float f = p[HH];
        hv = f * hv + (1.0f - f) * z;
        A *= f;
        p += NOUT;
    }
    int o = (b * NC + ch) * HH + h;
    g_cA[o] = A;
    g_cB[o] = hv;
}

// pass 2: sequential combine of chunk carries; writes h_start per chunk and hT.
// grid 16, block 256.
__global__ void scan_pass2(float* __restrict__ hT)
{
    int gid = blockIdx.x * blockDim.x + threadIdx.x;  // 0..4095
    int b = gid >> 9, h = gid & 511;
    float hr = 0.0f;
#pragma unroll
    for (int j = 0; j < NC; j++) {
        int o = (b * NC + j) * HH + h;
        g_hs[o] = hr;
        hr = g_cA[o] * hr + g_cB[o];
    }
    hT[b * HH + h] = hr;
}

// pass 3: replay scan with correct h0; out = o * h.
// grid 512, block 128. layer 0 -> g_out1, layer 1 -> dout.
__global__ void __launch_bounds__(128) scan_pass3(int layer, float* __restrict__ dout)
{
    int h  = (blockIdx.x & 3) * 128 + threadIdx.x;
    int ch = (blockIdx.x >> 2) & 15;
    int b  = blockIdx.x >> 6;
    const float* p = g_zfo + ((size_t)(b * TT + ch * LCH)) * NOUT + h;
    float* po = (layer ? dout : g_out1) + ((size_t)(b * TT + ch * LCH)) * HH + h;
    float hv = g_hs[(b * NC + ch) * HH + h];
#pragma unroll 4
    for (int i = 0; i < LCH; i++) {
        float z = p[0];
        float f = p[HH];
        float o = p[2 * HH];
        hv = f * hv + (1.0f - f) * z;
        *po = o * hv;
        p += NOUT;
        po += HH;
    }
}

extern "C" void kernel_launch(void* const* d_in, const int* in_sizes, int n_in,
                              void* d_out, int out_size)
{
    const float* x  = (const float*)d_in[0];
    const float* w0 = (const float*)d_in[1];
    const float* b0 = (const float*)d_in[2];
    const float* w1 = (const float*)d_in[3];
    const float* b1 = (const float*)d_in[4];

    float* out2 = (float*)d_out;                        // [B,T,H]
    float* h0   = out2 + (size_t)BB * TT * HH;          // [B,H]
    float* h1   = h0 + BB * HH;                         // [B,H]

    dim3 gg(256, 12);

    // layer 1
    qrnn_gemm<<<gg, 256>>>(0, x, w0, b0);
    scan_pass1<<<512, 128>>>();
    scan_pass2<<<16, 256>>>(h0);
    scan_pass3<<<512, 128>>>(0, nullptr);

    // layer 2
    qrnn_gemm<<<gg, 256>>>(1, x, w1, b1);
    scan_pass1<<<512, 128>>>();
    scan_pass2<<<16, 256>>>(h1);
    scan_pass3<<<512, 128>>>(1, out2);
}

// round 2
// speedup vs baseline: 1.5715x; 1.5715x over previous
#include <cuda_runtime.h>
#include <math.h>

#define BB   8
#define TT   4096
#define CC   512
#define HH   512
#define NOUT 1536
#define NC   64
#define LCH  64     // TT / NC

#define BM 128
#define BN 128
#define BK 16
#define STG 3
#define XPAD 20                       // 20 floats = 80B stride: float4-aligned + conflict-free frags
#define SX_SIZE (129 * XPAD)          // 2580 floats
#define SW_SIZE (2 * BN * XPAD)       // 5120 floats
#define STAGE_FLOATS (SX_SIZE + SW_SIZE)  // 7700
#define SMEM_BYTES (STG * STAGE_FLOATS * 4)

// -------- scratch (device globals; no allocation allowed) --------
__device__ __align__(16) float g_x   [BB * TT * CC];       // tf32-rounded input x
__device__ __align__(16) float g_w   [2 * 2 * NOUT * CC];  // [layer][tap][n][c], tf32-rounded
__device__ __align__(16) float g_zfo [BB * TT * NOUT];     // post-activation z|f|o
__device__ __align__(16) float g_out1[BB * TT * HH];       // layer-1 output (tf32-rounded)
__device__ __align__(16) float g_cA  [BB * NC * HH];
__device__ __align__(16) float g_cB  [BB * NC * HH];
__device__ __align__(16) float g_hs  [BB * NC * HH];

__device__ __forceinline__ float tfr(float x) {
    unsigned u;
    asm("cvt.rna.tf32.f32 %0, %1;" : "=r"(u) : "f"(x));
    return __uint_as_float(u);
}

__device__ __forceinline__ void mma8(float* c, const unsigned* a, unsigned b0, unsigned b1) {
    asm volatile(
        "mma.sync.aligned.m16n8k8.row.col.f32.tf32.tf32.f32 "
        "{%0,%1,%2,%3}, {%4,%5,%6,%7}, {%8,%9}, {%0,%1,%2,%3};\n"
        : "+f"(c[0]), "+f"(c[1]), "+f"(c[2]), "+f"(c[3])
        : "r"(a[0]), "r"(a[1]), "r"(a[2]), "r"(a[3]), "r"(b0), "r"(b1));
}

__device__ __forceinline__ void cpa16(float* dst, const float* src, bool pred) {
    unsigned d = (unsigned)__cvta_generic_to_shared(dst);
    int sz = pred ? 16 : 0;
    asm volatile("cp.async.cg.shared.global [%0], [%1], 16, %2;\n"
                 :: "r"(d), "l"(src), "r"(sz) : "memory");
}

__device__ __forceinline__ float fsigmoid(float x) { return 1.0f / (1.0f + __expf(-x)); }
__device__ __forceinline__ float ftanh(float x)    { return 2.0f / (1.0f + __expf(-2.0f * x)) - 1.0f; }
__device__ __forceinline__ float act(float v, int ng) { return (ng < HH) ? ftanh(v) : fsigmoid(v); }

// ---------------- prep: tf32 pre-rounding ----------------
__global__ void cvt_x(const float* __restrict__ x) {
    int gid = blockIdx.x * blockDim.x + threadIdx.x;   // BB*TT*CC/4 threads
    float4 v = ((const float4*)x)[gid];
    v.x = tfr(v.x); v.y = tfr(v.y); v.z = tfr(v.z); v.w = tfr(v.w);
    ((float4*)g_x)[gid] = v;
}

__global__ void cvt_w(const float* __restrict__ w0, const float* __restrict__ w1) {
    int gid = blockIdx.x * blockDim.x + threadIdx.x;   // 2*NOUT*CC threads
    int layer = gid >= NOUT * CC;
    int r = gid - layer * NOUT * CC;
    int n = r / CC, c = r % CC;
    const float* w = layer ? w1 : w0;
    float2 v = *(const float2*)(w + ((size_t)n * CC + c) * 2);
    g_w[(((size_t)layer * 2 + 0) * NOUT + n) * CC + c] = tfr(v.x);
    g_w[(((size_t)layer * 2 + 1) * NOUT + n) * CC + c] = tfr(v.y);
}

// ---------------- GEMM + activation ----------------
// ZFO[b,t,n] = act( sum_c W[n,c,0]*X[b,t-1,c] + W[n,c,1]*X[b,t,c] + bias[n] )
__global__ void __launch_bounds__(256, 2) qrnn_gemm(int layer, const float* __restrict__ bias)
{
    extern __shared__ float smem[];

    const float* X  = layer ? g_out1 : g_x;
    const float* Wl = g_w + (size_t)layer * 2 * NOUT * CC;

    const int tid  = threadIdx.x;
    const int mt   = blockIdx.x;
    const int nt   = blockIdx.y;
    const int b    = mt >> 5;
    const int t0   = (mt & 31) * BM;
    const int warp = tid >> 5, lane = tid & 31;
    const int wm   = warp >> 2, wn = warp & 3;
    const int gr   = lane >> 2, tg = lane & 3;

    const float* Xb = X + (size_t)b * TT * CC;

    float acc[4][4][4];
#pragma unroll
    for (int i = 0; i < 4; i++)
#pragma unroll
        for (int j = 0; j < 4; j++)
#pragma unroll
            for (int q = 0; q < 4; q++) acc[i][j][q] = 0.0f;

    // ---- stage loader ----
    auto load_stage = [&](int stage, int kc) {
        float* sX = smem + stage * STAGE_FLOATS;
        float* sW = sX + SX_SIZE;
        // X tile: rows t0-1 .. t0+127 (129 rows x 16 c), 516 16B chunks
        for (int idx = tid; idx < 516; idx += 256) {
            int r = idx >> 2, c4 = idx & 3;
            int t = t0 - 1 + r;
            const float* src = Xb + (size_t)(t < 0 ? 0 : t) * CC + kc + c4 * 4;
            cpa16(&sX[r * XPAD + c4 * 4], src, t >= 0);
        }
        // W tile: 2 taps x 128 n x 16 c, 1024 chunks
        for (int idx = tid; idx < 1024; idx += 256) {
            int tap = idx >> 9, rem = idx & 511, n = rem >> 2, c4 = rem & 3;
            const float* src = Wl + ((size_t)tap * NOUT + nt * BN + n) * CC + kc + c4 * 4;
            cpa16(&sW[(tap * BN + n) * XPAD + c4 * 4], src, true);
        }
        asm volatile("cp.async.commit_group;\n" ::: "memory");
    };

    load_stage(0, 0);
    load_stage(1, BK);

    for (int kt = 0; kt < 32; kt++) {
        if (kt == 31) asm volatile("cp.async.wait_group 0;\n" ::: "memory");
        else          asm volatile("cp.async.wait_group 1;\n" ::: "memory");
        __syncthreads();

        if (kt + 2 < 32) load_stage((kt + 2) % STG, (kt + 2) * BK);

        const unsigned* sX = (const unsigned*)(smem + (kt % STG) * STAGE_FLOATS);
        const unsigned* sW = sX + SX_SIZE;

#pragma unroll
        for (int k8 = 0; k8 < 2; ++k8) {
            int cb = k8 * 8;
#pragma unroll
            for (int tap = 0; tap < 2; ++tap) {
                unsigned a[4][4];
#pragma unroll
                for (int i = 0; i < 4; i++) {
                    int r0 = wm * 64 + i * 16 + gr + tap;
                    a[i][0] = sX[r0 * XPAD + cb + tg];
                    a[i][1] = sX[(r0 + 8) * XPAD + cb + tg];
                    a[i][2] = sX[r0 * XPAD + cb + tg + 4];
                    a[i][3] = sX[(r0 + 8) * XPAD + cb + tg + 4];
                }
#pragma unroll
                for (int j = 0; j < 4; j++) {
                    int n0 = wn * 32 + j * 8 + gr;
                    unsigned b0 = sW[(tap * BN + n0) * XPAD + cb + tg];
                    unsigned b1 = sW[(tap * BN + n0) * XPAD + cb + tg + 4];
#pragma unroll
                    for (int i = 0; i < 4; i++) mma8(acc[i][j], a[i], b0, b1);
                }
            }
        }
        __syncthreads();
    }

    // ---- epilogue ----
#pragma unroll
    for (int j = 0; j < 4; j++) {
        int ng = nt * BN + wn * 32 + j * 8 + tg * 2;
        float2 bb = *(const float2*)(bias + ng);
#pragma unroll
        for (int i = 0; i < 4; i++) {
            int m0 = wm * 64 + i * 16 + gr;
            size_t rowA = ((size_t)(b * TT + t0 + m0)) * NOUT;
            size_t rowB = ((size_t)(b * TT + t0 + m0 + 8)) * NOUT;
            float2 vA = make_float2(act(acc[i][j][0] + bb.x, ng), act(acc[i][j][1] + bb.y, ng + 1));
            float2 vB = make_float2(act(acc[i][j][2] + bb.x, ng), act(acc[i][j][3] + bb.y, ng + 1));
            *(float2*)&g_zfo[rowA + ng] = vA;
            *(float2*)&g_zfo[rowB + ng] = vB;
        }
    }
}

// ---------------- scans ----------------
// pass1: per (b, chunk) block, thread handles 4 h-channels. grid BB*NC=512, block 128.
__global__ void __launch_bounds__(128) scan_pass1()
{
    int b  = blockIdx.x >> 6;
    int ch = blockIdx.x & 63;
    int h4 = threadIdx.x * 4;
    const float* p = g_zfo + ((size_t)(b * TT + ch * LCH)) * NOUT + h4;
    float4 A  = make_float4(1.f, 1.f, 1.f, 1.f);
    float4 hv = make_float4(0.f, 0.f, 0.f, 0.f);
#pragma unroll 8
    for (int i = 0; i < LCH; i++) {
        float4 z = *(const float4*)p;
        float4 f = *(const float4*)(p + HH);
        hv.x = f.x * hv.x + (1.0f - f.x) * z.x;  A.x *= f.x;
        hv.y = f.y * hv.y + (1.0f - f.y) * z.y;  A.y *= f.y;
        hv.z = f.z * hv.z + (1.0f - f.z) * z.z;  A.z *= f.z;
        hv.w = f.w * hv.w + (1.0f - f.w) * z.w;  A.w *= f.w;
        p += NOUT;
    }
    int o = (b * NC + ch) * HH + h4;
    *(float4*)&g_cA[o] = A;
    *(float4*)&g_cB[o] = hv;
}

// pass2: sequential combine. grid 16, block 256 (4096 threads = B*H).
__global__ void scan_pass2(float* __restrict__ hT)
{
    int gid = blockIdx.x * blockDim.x + threadIdx.x;
    int b = gid >> 9, h = gid & 511;
    float hr = 0.0f;
#pragma unroll
    for (int j = 0; j < NC; j++) {
        int o = (b * NC + j) * HH + h;
        g_hs[o] = hr;
        hr = g_cA[o] * hr + g_cB[o];
    }
    hT[b * HH + h] = hr;
}

// pass3: replay with correct h0; out = o*h. Layer0 writes tf32-rounded g_out1.
__global__ void __launch_bounds__(128) scan_pass3(int layer, float* __restrict__ dout)
{
    int b  = blockIdx.x >> 6;
    int ch = blockIdx.x & 63;
    int h4 = threadIdx.x * 4;
    const float* p = g_zfo + ((size_t)(b * TT + ch * LCH)) * NOUT + h4;
    float* po = (layer ? dout : g_out1) + ((size_t)(b * TT + ch * LCH)) * HH + h4;
    float4 hv = *(const float4*)&g_hs[(b * NC + ch) * HH + h4];
#pragma unroll 8
    for (int i = 0; i < LCH; i++) {
        float4 z = *(const float4*)p;
        float4 f = *(const float4*)(p + HH);
        float4 o = *(const float4*)(p + 2 * HH);
        hv.x = f.x * hv.x + (1.0f - f.x) * z.x;
        hv.y = f.y * hv.y + (1.0f - f.y) * z.y;
        hv.z = f.z * hv.z + (1.0f - f.z) * z.z;
        hv.w = f.w * hv.w + (1.0f - f.w) * z.w;
        float4 r = make_float4(o.x * hv.x, o.y * hv.y, o.z * hv.z, o.w * hv.w);
        if (!layer) { r.x = tfr(r.x); r.y = tfr(r.y); r.z = tfr(r.z); r.w = tfr(r.w); }
        *(float4*)po = r;
        p  += NOUT;
        po += HH;
    }
}

extern "C" void kernel_launch(void* const* d_in, const int* in_sizes, int n_in,
                              void* d_out, int out_size)
{
    const float* x  = (const float*)d_in[0];
    const float* b0 = (const float*)d_in[2];
    const float* w0 = (const float*)d_in[1];
    const float* w1 = (const float*)d_in[3];
    const float* b1 = (const float*)d_in[4];

    float* out2 = (float*)d_out;
    float* h0   = out2 + (size_t)BB * TT * HH;
    float* h1   = h0 + BB * HH;

    cudaFuncSetAttribute(qrnn_gemm, cudaFuncAttributeMaxDynamicSharedMemorySize, SMEM_BYTES);

    cvt_x<<<BB * TT * CC / 4 / 256, 256>>>(x);
    cvt_w<<<2 * NOUT * CC / 256, 256>>>(w0, w1);

    dim3 gg(256, 12);

    qrnn_gemm<<<gg, 256, SMEM_BYTES>>>(0, b0);
    scan_pass1<<<BB * NC, 128>>>();
    scan_pass2<<<16, 256>>>(h0);
    scan_pass3<<<BB * NC, 128>>>(0, nullptr);

    qrnn_gemm<<<gg, 256, SMEM_BYTES>>>(1, b1);
    scan_pass1<<<BB * NC, 128>>>();
    scan_pass2<<<16, 256>>>(h1);
    scan_pass3<<<BB * NC, 128>>>(1, out2);
}

// round 4
// speedup vs baseline: 2.5519x; 1.6239x over previous
#include <cuda_runtime.h>
#include <cuda_fp16.h>
#include <math.h>

#define BB 8
#define TT 4096
#define CC 512
#define HH 512
#define NOUT 1536
#define NC 64
#define LCH 64

#define BM 128
#define BN 128
#define BK 32                 // halves per k-tile
#define NKT 16                // 512 / 32
#define STG 3
#define XPAD 20               // row stride in b32 units (conflict-free)
#define SX_U32 (129 * XPAD)   // 2580
#define SW_U32 (256 * XPAD)   // 5120
#define STAGE_U32 (SX_U32 + SW_U32)
#define SMEM_BYTES (STG * STAGE_U32 * 4)

// -------- scratch --------
__device__ __align__(16) __half g_xh [(size_t)BB * TT * CC];      // fp16 input x
__device__ __align__(16) __half g_xh2[(size_t)BB * TT * CC];      // fp16 layer-1 output
__device__ __align__(16) __half g_wh [(size_t)2 * 2 * NOUT * CC]; // [layer][tap][n][c]
__device__ __align__(16) float  g_zfo[(size_t)BB * TT * NOUT];    // post-activation z|f|o (fp32)
__device__ __align__(16) float  g_cA [BB * NC * HH];
__device__ __align__(16) float  g_cB [BB * NC * HH];
__device__ __align__(16) float  g_hs [BB * NC * HH];

__device__ __forceinline__ void cpa16(unsigned* dst_smem_word, const void* src, bool pred) {
    unsigned d = (unsigned)__cvta_generic_to_shared(dst_smem_word);
    int sz = pred ? 16 : 0;
    asm volatile("cp.async.cg.shared.global [%0], [%1], 16, %2;\n"
                 :: "r"(d), "l"(src), "r"(sz) : "memory");
}

__device__ __forceinline__ void mma16(float* c, const unsigned* a, unsigned b0, unsigned b1) {
    asm volatile(
        "mma.sync.aligned.m16n8k16.row.col.f32.f16.f16.f32 "
        "{%0,%1,%2,%3}, {%4,%5,%6,%7}, {%8,%9}, {%0,%1,%2,%3};\n"
        : "+f"(c[0]), "+f"(c[1]), "+f"(c[2]), "+f"(c[3])
        : "r"(a[0]), "r"(a[1]), "r"(a[2]), "r"(a[3]), "r"(b0), "r"(b1));
}

__device__ __forceinline__ float fsigmoid(float x) { return 1.0f / (1.0f + __expf(-x)); }
__device__ __forceinline__ float ftanh(float x)    { return 2.0f / (1.0f + __expf(-2.0f * x)) - 1.0f; }

// ---------------- prep: fp16 conversion ----------------
// 8 floats -> 8 halves per thread.  two launches of 4096 blocks each.
__global__ void cvt_x(const float* __restrict__ x, int base) {
    int gid = base + blockIdx.x * blockDim.x + threadIdx.x;
    float4 v0 = ((const float4*)x)[gid * 2];
    float4 v1 = ((const float4*)x)[gid * 2 + 1];
    __half2 h0 = __floats2half2_rn(v0.x, v0.y);
    __half2 h1 = __floats2half2_rn(v0.z, v0.w);
    __half2 h2 = __floats2half2_rn(v1.x, v1.y);
    __half2 h3 = __floats2half2_rn(v1.z, v1.w);
    uint4 o;
    o.x = *(unsigned*)&h0; o.y = *(unsigned*)&h1;
    o.z = *(unsigned*)&h2; o.w = *(unsigned*)&h3;
    ((uint4*)g_xh)[gid] = o;
}

__global__ void cvt_w(const float* __restrict__ w0, const float* __restrict__ w1) {
    int gid = blockIdx.x * blockDim.x + threadIdx.x;  // 2*NOUT*CC
    int layer = gid >= NOUT * CC;
    int r = gid - layer * NOUT * CC;
    int n = r / CC, c = r % CC;
    const float* w = layer ? w1 : w0;
    float2 v = *(const float2*)(w + ((size_t)n * CC + c) * 2);
    g_wh[(((size_t)layer * 2 + 0) * NOUT + n) * CC + c] = __float2half_rn(v.x); // tap0 -> x[t-1]
    g_wh[(((size_t)layer * 2 + 1) * NOUT + n) * CC + c] = __float2half_rn(v.y); // tap1 -> x[t]
}

// ---------------- fp16 HMMA GEMM + activation ----------------
// ZFO[b,t,n] = act( sum_c W[n,c,0]*X[b,t-1,c] + W[n,c,1]*X[b,t,c] + bias[n] )
// grid (12, 256): x = N-tile (fast: shares A stripe via L2), y = M-tile. block 256.
__global__ void __launch_bounds__(256, 2) qrnn_gemm(int layer, const float* __restrict__ bias)
{
    extern __shared__ unsigned smem[];

    const __half* X  = layer ? g_xh2 : g_xh;
    const __half* Wl = g_wh + (size_t)layer * 2 * NOUT * CC;

    const int tid  = threadIdx.x;
    const int nt   = blockIdx.x;
    const int mt   = blockIdx.y;
    const int b    = mt >> 5;
    const int t0   = (mt & 31) * BM;
    const int warp = tid >> 5, lane = tid & 31;
    const int wm   = warp >> 2, wn = warp & 3;
    const int gr   = lane >> 2, tg = lane & 3;

    const __half* Xb = X + (size_t)b * TT * CC;

    float acc[4][4][4];
#pragma unroll
    for (int i = 0; i < 4; i++)
#pragma unroll
        for (int j = 0; j < 4; j++)
#pragma unroll
            for (int q = 0; q < 4; q++) acc[i][j][q] = 0.0f;

    auto load_stage = [&](int stage, int kt) {
        unsigned* sX = smem + stage * STAGE_U32;
        unsigned* sW = sX + SX_U32;
        int kc = kt * BK;
        // X tile: 129 rows (t0-1 .. t0+127) x 32 halves; 4 x 16B chunks/row
        for (int idx = tid; idx < 516; idx += 256) {
            int r = idx >> 2, c4 = idx & 3;
            int t = t0 - 1 + r;
            const __half* src = Xb + (size_t)(t < 0 ? 0 : t) * CC + kc + c4 * 8;
            cpa16(&sX[r * XPAD + c4 * 4], src, t >= 0);
        }
        // W tile: 2 taps x 128 n x 32 halves
        for (int idx = tid; idx < 1024; idx += 256) {
            int tap = idx >> 9, rem = idx & 511, n = rem >> 2, c4 = rem & 3;
            const __half* src = Wl + ((size_t)tap * NOUT + nt * BN + n) * CC + kc + c4 * 8;
            cpa16(&sW[(tap * BN + n) * XPAD + c4 * 4], src, true);
        }
        asm volatile("cp.async.commit_group;" ::: "memory");
    };

    load_stage(0, 0);
    load_stage(1, 1);

    for (int kt = 0; kt < NKT; kt++) {
        if (kt == NKT - 1) asm volatile("cp.async.wait_group 0;" ::: "memory");
        else               asm volatile("cp.async.wait_group 1;" ::: "memory");
        __syncthreads();

        if (kt + 2 < NKT) load_stage((kt + 2) % STG, kt + 2);

        const unsigned* sX = smem + (kt % STG) * STAGE_U32;
        const unsigned* sW = sX + SX_U32;

#pragma unroll
        for (int k16 = 0; k16 < 2; ++k16) {
            int cb = k16 * 8;   // b32 offset of this 16-half chunk
#pragma unroll
            for (int tap = 0; tap < 2; ++tap) {
                unsigned a[4][4];
#pragma unroll
                for (int i = 0; i < 4; i++) {
                    int r0 = wm * 64 + i * 16 + gr + tap;
                    a[i][0] = sX[r0 * XPAD + cb + tg];            // row, k-lo
                    a[i][1] = sX[(r0 + 8) * XPAD + cb + tg];      // row+8, k-lo
                    a[i][2] = sX[r0 * XPAD + cb + tg + 4];        // row, k-hi
                    a[i][3] = sX[(r0 + 8) * XPAD + cb + tg + 4];  // row+8, k-hi
                }
#pragma unroll
                for (int j = 0; j < 4; j++) {
                    int n0 = wn * 32 + j * 8 + gr;
                    unsigned b0 = sW[(tap * BN + n0) * XPAD + cb + tg];
                    unsigned b1 = sW[(tap * BN + n0) * XPAD + cb + tg + 4];
#pragma unroll
                    for (int i = 0; i < 4; i++) mma16(acc[i][j], a[i], b0, b1);
                }
            }
        }
        __syncthreads();
    }

    // ---- epilogue: bias + activation -> g_zfo (fp32) ----
#pragma unroll
    for (int j = 0; j < 4; j++) {
        int ng = nt * BN + wn * 32 + j * 8 + tg * 2;
        float2 bb = *(const float2*)(bias + ng);
#pragma unroll
        for (int i = 0; i < 4; i++) {
            int m0 = wm * 64 + i * 16 + gr;
            size_t rowA = ((size_t)(b * TT + t0 + m0)) * NOUT;
            size_t rowB = ((size_t)(b * TT + t0 + m0 + 8)) * NOUT;
            float aA0 = acc[i][j][0] + bb.x, aA1 = acc[i][j][1] + bb.y;
            float aB0 = acc[i][j][2] + bb.x, aB1 = acc[i][j][3] + bb.y;
            bool isz = (ng < HH);
            float2 vA = make_float2(isz ? ftanh(aA0) : fsigmoid(aA0),
                                    (ng + 1 < HH) ? ftanh(aA1) : fsigmoid(aA1));
            float2 vB = make_float2(isz ? ftanh(aB0) : fsigmoid(aB0),
                                    (ng + 1 < HH) ? ftanh(aB1) : fsigmoid(aB1));
            *(float2*)&g_zfo[rowA + ng] = vA;
            *(float2*)&g_zfo[rowB + ng] = vB;
        }
    }
}

// ---------------- scans ----------------
__global__ void __launch_bounds__(128) scan_pass1()
{
    int b  = blockIdx.x >> 6;
    int ch = blockIdx.x & 63;
    int h4 = threadIdx.x * 4;
    const float* p = g_zfo + ((size_t)(b * TT + ch * LCH)) * NOUT + h4;
    float4 A  = make_float4(1.f, 1.f, 1.f, 1.f);
    float4 hv = make_float4(0.f, 0.f, 0.f, 0.f);
#pragma unroll 8
    for (int i = 0; i < LCH; i++) {
        float4 z = *(const float4*)p;
        float4 f = *(const float4*)(p + HH);
        hv.x = f.x * hv.x + (1.0f - f.x) * z.x;  A.x *= f.x;
        hv.y = f.y * hv.y + (1.0f - f.y) * z.y;  A.y *= f.y;
        hv.z = f.z * hv.z + (1.0f - f.z) * z.z;  A.z *= f.z;
        hv.w = f.w * hv.w + (1.0f - f.w) * z.w;  A.w *= f.w;
        p += NOUT;
    }
    int o = (b * NC + ch) * HH + h4;
    *(float4*)&g_cA[o] = A;
    *(float4*)&g_cB[o] = hv;
}

__global__ void scan_pass2(float* __restrict__ hT)
{
    int gid = blockIdx.x * blockDim.x + threadIdx.x;
    int b = gid >> 9, h = gid & 511;
    float hr = 0.0f;
#pragma unroll
    for (int j = 0; j < NC; j++) {
        int o = (b * NC + j) * HH + h;
        g_hs[o] = hr;
        hr = g_cA[o] * hr + g_cB[o];
    }
    hT[b * HH + h] = hr;
}

// layer 0: writes fp16 g_xh2.  layer 1: writes fp32 d_out.
__global__ void __launch_bounds__(128) scan_pass3(int layer, float* __restrict__ dout)
{
    int b  = blockIdx.x >> 6;
    int ch = blockIdx.x & 63;
    int h4 = threadIdx.x * 4;
    const float* p = g_zfo + ((size_t)(b * TT + ch * LCH)) * NOUT + h4;
    float4 hv = *(const float4*)&g_hs[(b * NC + ch) * HH + h4];
#pragma unroll 4
    for (int i = 0; i < LCH; i++) {
        int t = ch * LCH + i;
        float4 z = *(const float4*)p;
        float4 f = *(const float4*)(p + HH);
        float4 o = *(const float4*)(p + 2 * HH);
        hv.x = f.x * hv.x + (1.0f - f.x) * z.x;
        hv.y = f.y * hv.y + (1.0f - f.y) * z.y;
        hv.z = f.z * hv.z + (1.0f - f.z) * z.z;
        hv.w = f.w * hv.w + (1.0f - f.w) * z.w;
        float4 r = make_float4(o.x * hv.x, o.y * hv.y, o.z * hv.z, o.w * hv.w);
        if (!layer) {
            __half2 p0 = __floats2half2_rn(r.x, r.y);
            __half2 p1 = __floats2half2_rn(r.z, r.w);
            uint2 st;
            st.x = *(unsigned*)&p0;
            st.y = *(unsigned*)&p1;
            *(uint2*)&g_xh2[((size_t)b * TT + t) * CC + h4] = st;
        } else {
            *(float4*)&dout[((size_t)b * TT + t) * HH + h4] = r;
        }
        p += NOUT;
    }
}

extern "C" void kernel_launch(void* const* d_in, const int* in_sizes, int n_in,
                              void* d_out, int out_size)
{
    const float* x  = (const float*)d_in[0];
    const float* w0 = (const float*)d_in[1];
    const float* b0 = (const float*)d_in[2];
    const float* w1 = (const float*)d_in[3];
    const float* b1 = (const float*)d_in[4];

    float* out2 = (float*)d_out;
    float* h0   = out2 + (size_t)BB * TT * HH;
    float* h1   = h0 + BB * HH;

    cudaFuncSetAttribute(qrnn_gemm, cudaFuncAttributeMaxDynamicSharedMemorySize, SMEM_BYTES);

    cvt_x<<<4096, 256>>>(x, 0);
    cvt_x<<<4096, 256>>>(x, 4096 * 256);
    cvt_w<<<2 * NOUT * CC / 256, 256>>>(w0, w1);

    dim3 gg(NOUT / BN, BB * TT / BM);   // (12, 256)

    qrnn_gemm<<<gg, 256, SMEM_BYTES>>>(0, b0);
    scan_pass1<<<BB * NC, 128>>>();
    scan_pass2<<<16, 256>>>(h0);
    scan_pass3<<<BB * NC, 128>>>(0, nullptr);

    qrnn_gemm<<<gg, 256, SMEM_BYTES>>>(1, b1);
    scan_pass1<<<BB * NC, 128>>>();
    scan_pass2<<<16, 256>>>(h1);
    scan_pass3<<<BB * NC, 128>>>(1, out2);
}

// round 5
// speedup vs baseline: 2.7300x; 1.0698x over previous
#include <cuda_runtime.h>
#include <cuda_fp16.h>
#include <math.h>

#define BB 8
#define TT 4096
#define CC 512
#define HH 512
#define NOUT 1536
#define NC 64
#define LCH 64

#define BM 128
#define BN 128
#define BK 32                 // halves per k-tile
#define NKT 16                // 512 / 32
#define STG 3
#define XPAD 20               // row stride in b32 units (conflict-free, 16B-aligned)
#define SX_U32 (129 * XPAD)   // 2580
#define SW_U32 (256 * XPAD)   // 5120
#define STAGE_U32 (SX_U32 + SW_U32)
#define SMEM_BYTES (STG * STAGE_U32 * 4)

// -------- scratch --------
__device__ __align__(16) __half g_xh [(size_t)BB * TT * CC];      // fp16 input x
__device__ __align__(16) __half g_xh2[(size_t)BB * TT * CC];      // fp16 layer-1 output
__device__ __align__(16) __half g_wh [(size_t)2 * 2 * NOUT * CC]; // [layer][tap][n][c]
__device__ __align__(16) float  g_zfo[(size_t)BB * TT * NOUT];    // post-activation z|f|o (fp32)
__device__ __align__(16) float  g_cA [BB * NC * HH];
__device__ __align__(16) float  g_cB [BB * NC * HH];
__device__ __align__(16) float  g_hs [BB * NC * HH];

__device__ __forceinline__ void cpa16(unsigned* dst_smem_word, const void* src, bool pred) {
    unsigned d = (unsigned)__cvta_generic_to_shared(dst_smem_word);
    int sz = pred ? 16 : 0;
    asm volatile("cp.async.cg.shared.global [%0], [%1], 16, %2;\n"
                 :: "r"(d), "l"(src), "r"(sz) : "memory");
}

__device__ __forceinline__ void mma16(float* c, const unsigned* a, unsigned b0, unsigned b1) {
    asm volatile(
        "mma.sync.aligned.m16n8k16.row.col.f32.f16.f16.f32 "
        "{%0,%1,%2,%3}, {%4,%5,%6,%7}, {%8,%9}, {%0,%1,%2,%3};\n"
        : "+f"(c[0]), "+f"(c[1]), "+f"(c[2]), "+f"(c[3])
        : "r"(a[0]), "r"(a[1]), "r"(a[2]), "r"(a[3]), "r"(b0), "r"(b1));
}

__device__ __forceinline__ void ldsm4(unsigned* r, unsigned addr) {
    asm volatile("ldmatrix.sync.aligned.m8n8.x4.shared.b16 {%0,%1,%2,%3}, [%4];"
                 : "=r"(r[0]), "=r"(r[1]), "=r"(r[2]), "=r"(r[3]) : "r"(addr));
}

__device__ __forceinline__ float fsigmoid(float x) { return 1.0f / (1.0f + __expf(-x)); }
__device__ __forceinline__ float ftanh(float x)    { return 2.0f / (1.0f + __expf(-2.0f * x)) - 1.0f; }

// ---------------- prep: fp16 conversion ----------------
__global__ void cvt_x(const float* __restrict__ x) {
    int gid = blockIdx.x * blockDim.x + threadIdx.x;   // BB*TT*CC/8 threads
    float4 v0 = ((const float4*)x)[gid * 2];
    float4 v1 = ((const float4*)x)[gid * 2 + 1];
    __half2 h0 = __floats2half2_rn(v0.x, v0.y);
    __half2 h1 = __floats2half2_rn(v0.z, v0.w);
    __half2 h2 = __floats2half2_rn(v1.x, v1.y);
    __half2 h3 = __floats2half2_rn(v1.z, v1.w);
    uint4 o;
    o.x = *(unsigned*)&h0; o.y = *(unsigned*)&h1;
    o.z = *(unsigned*)&h2; o.w = *(unsigned*)&h3;
    ((uint4*)g_xh)[gid] = o;
}

__global__ void cvt_w(const float* __restrict__ w0, const float* __restrict__ w1) {
    int gid = blockIdx.x * blockDim.x + threadIdx.x;  // 2*NOUT*CC
    int layer = gid >= NOUT * CC;
    int r = gid - layer * NOUT * CC;
    int n = r / CC, c = r % CC;
    const float* w = layer ? w1 : w0;
    float2 v = *(const float2*)(w + ((size_t)n * CC + c) * 2);
    g_wh[(((size_t)layer * 2 + 0) * NOUT + n) * CC + c] = __float2half_rn(v.x); // tap0 -> x[t-1]
    g_wh[(((size_t)layer * 2 + 1) * NOUT + n) * CC + c] = __float2half_rn(v.y); // tap1 -> x[t]
}

// ---------------- fp16 HMMA GEMM + activation ----------------
// ZFO[b,t,n] = act( sum_c W[n,c,0]*X[b,t-1,c] + W[n,c,1]*X[b,t,c] + bias[n] )
// grid (12, 256): x = N-tile (fast: shares A stripe via L2), y = M-tile. block 256.
__global__ void __launch_bounds__(256, 2) qrnn_gemm(int layer, const float* __restrict__ bias)
{
    extern __shared__ unsigned smem[];

    const __half* X  = layer ? g_xh2 : g_xh;
    const __half* Wl = g_wh + (size_t)layer * 2 * NOUT * CC;

    const int tid  = threadIdx.x;
    const int nt   = blockIdx.x;
    const int mt   = blockIdx.y;
    const int b    = mt >> 5;
    const int t0   = (mt & 31) * BM;
    const int warp = tid >> 5, lane = tid & 31;
    const int wm   = warp >> 2, wn = warp & 3;
    const int gr   = lane >> 2, tg = lane & 3;

    const __half* Xb = X + (size_t)b * TT * CC;

    float acc[4][4][4];
#pragma unroll
    for (int i = 0; i < 4; i++)
#pragma unroll
        for (int j = 0; j < 4; j++)
#pragma unroll
            for (int q = 0; q < 4; q++) acc[i][j][q] = 0.0f;

    // ---- per-lane ldmatrix base addresses (bytes into stage 0) ----
    const unsigned smem_b = (unsigned)__cvta_generic_to_shared(smem);
    // A x4: m0 rows r0..r0+7 k-lo | m1 rows +8 k-lo | m2 rows r0.. k-hi | m3 rows +8 k-hi
    const int a_off = (wm * 64 + (lane & 7) + ((lane >> 3) & 1) * 8) * XPAD
                    + ((lane >> 4) & 1) * 4;
    // B x4 (covers j-pair): m0 rows n..n+7 k-lo | m1 same rows k-hi | m2 rows +8 k-lo | m3 +8 k-hi
    const int b_off = (wn * 32 + ((lane >> 4) & 1) * 8 + (lane & 7)) * XPAD
                    + ((lane >> 3) & 1) * 4;
    const unsigned aAddr0 = smem_b + (unsigned)(a_off * 4);
    const unsigned bAddr0 = smem_b + (unsigned)((SX_U32 + b_off) * 4);

    auto load_stage = [&](int stage, int kt) {
        unsigned* sX = smem + stage * STAGE_U32;
        unsigned* sW = sX + SX_U32;
        int kc = kt * BK;
        for (int idx = tid; idx < 516; idx += 256) {          // X: 129 rows x 32 halves
            int r = idx >> 2, c4 = idx & 3;
            int t = t0 - 1 + r;
            const __half* src = Xb + (size_t)(t < 0 ? 0 : t) * CC + kc + c4 * 8;
            cpa16(&sX[r * XPAD + c4 * 4], src, t >= 0);
        }
        for (int idx = tid; idx < 1024; idx += 256) {         // W: 2 taps x 128 n x 32 halves
            int tap = idx >> 9, rem = idx & 511, n = rem >> 2, c4 = rem & 3;
            const __half* src = Wl + ((size_t)tap * NOUT + nt * BN + n) * CC + kc + c4 * 8;
            cpa16(&sW[(tap * BN + n) * XPAD + c4 * 4], src, true);
        }
        asm volatile("cp.async.commit_group;" ::: "memory");
    };

    load_stage(0, 0);
    load_stage(1, 1);

    for (int kt = 0; kt < NKT; kt++) {
        if (kt == NKT - 1) asm volatile("cp.async.wait_group 0;" ::: "memory");
        else               asm volatile("cp.async.wait_group 1;" ::: "memory");
        __syncthreads();

        if (kt + 2 < NKT) load_stage((kt + 2) % STG, kt + 2);

        const unsigned stageB = (unsigned)((kt % STG) * (STAGE_U32 * 4));
        const unsigned aS = aAddr0 + stageB;
        const unsigned bS = bAddr0 + stageB;

#pragma unroll
        for (int k16 = 0; k16 < 2; ++k16) {
#pragma unroll
            for (int tap = 0; tap < 2; ++tap) {
                unsigned afr[4][4], bfr[2][4];
#pragma unroll
                for (int i = 0; i < 4; i++)
                    ldsm4(afr[i], aS + (unsigned)((i * 16 * XPAD + tap * XPAD + k16 * 8) * 4));
#pragma unroll
                for (int jp = 0; jp < 2; jp++)
                    ldsm4(bfr[jp], bS + (unsigned)((jp * 16 * XPAD + tap * BN * XPAD + k16 * 8) * 4));
#pragma unroll
                for (int j = 0; j < 4; j++) {
                    unsigned b0 = bfr[j >> 1][(j & 1) * 2];
                    unsigned b1 = bfr[j >> 1][(j & 1) * 2 + 1];
#pragma unroll
                    for (int i = 0; i < 4; i++) mma16(acc[i][j], afr[i], b0, b1);
                }
            }
        }
    }

    // ---- epilogue: bias + activation -> g_zfo (fp32) ----
#pragma unroll
    for (int j = 0; j < 4; j++) {
        int ng = nt * BN + wn * 32 + j * 8 + tg * 2;
        float2 bb = *(const float2*)(bias + ng);
#pragma unroll
        for (int i = 0; i < 4; i++) {
            int m0 = wm * 64 + i * 16 + gr;
            size_t rowA = ((size_t)(b * TT + t0 + m0)) * NOUT;
            size_t rowB = ((size_t)(b * TT + t0 + m0 + 8)) * NOUT;
            float aA0 = acc[i][j][0] + bb.x, aA1 = acc[i][j][1] + bb.y;
            float aB0 = acc[i][j][2] + bb.x, aB1 = acc[i][j][3] + bb.y;
            bool isz = (ng < HH);
            float2 vA = make_float2(isz ? ftanh(aA0) : fsigmoid(aA0),
                                    (ng + 1 < HH) ? ftanh(aA1) : fsigmoid(aA1));
            float2 vB = make_float2(isz ? ftanh(aB0) : fsigmoid(aB0),
                                    (ng + 1 < HH) ? ftanh(aB1) : fsigmoid(aB1));
            *(float2*)&g_zfo[rowA + ng] = vA;
            *(float2*)&g_zfo[rowB + ng] = vB;
        }
    }
}

// ---------------- scans ----------------
__global__ void __launch_bounds__(128) scan_pass1()
{
    int b  = blockIdx.x >> 6;
    int ch = blockIdx.x & 63;
    int h4 = threadIdx.x * 4;
    const float* p = g_zfo + ((size_t)(b * TT + ch * LCH)) * NOUT + h4;
    float4 A  = make_float4(1.f, 1.f, 1.f, 1.f);
    float4 hv = make_float4(0.f, 0.f, 0.f, 0.f);
#pragma unroll 8
    for (int i = 0; i < LCH; i++) {
        float4 z = *(const float4*)p;
        float4 f = *(const float4*)(p + HH);
        hv.x = f.x * hv.x + (1.0f - f.x) * z.x;  A.x *= f.x;
        hv.y = f.y * hv.y + (1.0f - f.y) * z.y;  A.y *= f.y;
        hv.z = f.z * hv.z + (1.0f - f.z) * z.z;  A.z *= f.z;
        hv.w = f.w * hv.w + (1.0f - f.w) * z.w;  A.w *= f.w;
        p += NOUT;
    }
    int o = (b * NC + ch) * HH + h4;
    *(float4*)&g_cA[o] = A;
    *(float4*)&g_cB[o] = hv;
}

__global__ void scan_pass2(float* __restrict__ hT)
{
    int gid = blockIdx.x * blockDim.x + threadIdx.x;
    int b = gid >> 9, h = gid & 511;
    float hr = 0.0f;
#pragma unroll
    for (int j = 0; j < NC; j++) {
        int o = (b * NC + j) * HH + h;
        g_hs[o] = hr;
        hr = g_cA[o] * hr + g_cB[o];
    }
    hT[b * HH + h] = hr;
}

// layer 0: writes fp16 g_xh2.  layer 1: writes fp32 d_out.
__global__ void __launch_bounds__(128) scan_pass3(int layer, float* __restrict__ dout)
{
    int b  = blockIdx.x >> 6;
    int ch = blockIdx.x & 63;
    int h4 = threadIdx.x * 4;
    const float* p = g_zfo + ((size_t)(b * TT + ch * LCH)) * NOUT + h4;
    float4 hv = *(const float4*)&g_hs[(b * NC + ch) * HH + h4];
#pragma unroll 4
    for (int i = 0; i < LCH; i++) {
        int t = ch * LCH + i;
        float4 z = *(const float4*)p;
        float4 f = *(const float4*)(p + HH);
        float4 o = *(const float4*)(p + 2 * HH);
        hv.x = f.x * hv.x + (1.0f - f.x) * z.x;
        hv.y = f.y * hv.y + (1.0f - f.y) * z.y;
        hv.z = f.z * hv.z + (1.0f - f.z) * z.z;
        hv.w = f.w * hv.w + (1.0f - f.w) * z.w;
        float4 r = make_float4(o.x * hv.x, o.y * hv.y, o.z * hv.z, o.w * hv.w);
        if (!layer) {
            __half2 p0 = __floats2half2_rn(r.x, r.y);
            __half2 p1 = __floats2half2_rn(r.z, r.w);
            uint2 st;
            st.x = *(unsigned*)&p0;
            st.y = *(unsigned*)&p1;
            *(uint2*)&g_xh2[((size_t)b * TT + t) * CC + h4] = st;
        } else {
            *(float4*)&dout[((size_t)b * TT + t) * HH + h4] = r;
        }
        p += NOUT;
    }
}

extern "C" void kernel_launch(void* const* d_in, const int* in_sizes, int n_in,
                              void* d_out, int out_size)
{
    const float* x  = (const float*)d_in[0];
    const float* w0 = (const float*)d_in[1];
    const float* b0 = (const float*)d_in[2];
    const float* w1 = (const float*)d_in[3];
    const float* b1 = (const float*)d_in[4];

    float* out2 = (float*)d_out;
    float* h0   = out2 + (size_t)BB * TT * HH;
    float* h1   = h0 + BB * HH;

    cudaFuncSetAttribute(qrnn_gemm, cudaFuncAttributeMaxDynamicSharedMemorySize, SMEM_BYTES);

    cvt_x<<<BB * TT * CC / 8 / 256, 256>>>(x);
    cvt_w<<<2 * NOUT * CC / 256, 256>>>(w0, w1);

    dim3 gg(NOUT / BN, BB * TT / BM);   // (12, 256)

    qrnn_gemm<<<gg, 256, SMEM_BYTES>>>(0, b0);
    scan_pass1<<<BB * NC, 128>>>();
    scan_pass2<<<16, 256>>>(h0);
    scan_pass3<<<BB * NC, 128>>>(0, nullptr);

    qrnn_gemm<<<gg, 256, SMEM_BYTES>>>(1, b1);
    scan_pass1<<<BB * NC, 128>>>();
    scan_pass2<<<16, 256>>>(h1);
    scan_pass3<<<BB * NC, 128>>>(1, out2);
}